// round 1
// baseline (speedup 1.0000x reference)
#include <cuda_runtime.h>
#include <cstdint>
#include <cstddef>

#define B_  64
#define T_  512
#define I_  256
#define H_  512
#define G4  2048   // 4*H
#define O_  256

#define NCTA_SCAN 128
#define NTHR_SCAN 128

// ---------------- static scratch (allocation-free per rules) ----------------
__device__ float g_xp[(size_t)B_ * T_ * G4];     // x@W + bias, [B*T, 4H]  (256 MB)
__device__ float g_hseq[(size_t)B_ * T_ * H_];   // hidden_seq [B*T, H]    (64 MB)
__device__ float g_hbuf[2][H_ * B_];             // h double buffer, TRANSPOSED [k][b]
__device__ unsigned g_bar;

// ---------------- packed fp32x2 helpers (sm_103a FFMA2) ----------------
__device__ __forceinline__ unsigned long long pk2(float x, float y) {
    unsigned long long r;
    asm("mov.b64 %0, {%1,%2};" : "=l"(r) : "f"(x), "f"(y));
    return r;
}
__device__ __forceinline__ void fma2(unsigned long long& d, unsigned long long a, unsigned long long b) {
    asm("fma.rn.f32x2 %0, %1, %2, %0;" : "+l"(d) : "l"(a), "l"(b));
}
__device__ __forceinline__ float2 up2(unsigned long long v) {
    float lo, hi;
    asm("mov.b64 {%0,%1}, %2;" : "=f"(lo), "=f"(hi) : "l"(v));
    return make_float2(lo, hi);
}

__device__ __forceinline__ float sigmoidf_(float x) { return 1.0f / (1.0f + expf(-x)); }

// ---------------- init: zero h0 + barrier counter (every launch) ----------------
__global__ void init_kernel() {
    int i = blockIdx.x * blockDim.x + threadIdx.x;
    if (i < 2 * H_ * B_) ((float*)g_hbuf)[i] = 0.0f;
    if (i == 0) g_bar = 0u;
}

// ---------------- generic fp32 GEMM + bias: C[M,N] = A[M,K]@B[K,N] + bias ----------------
// BM=BN=128, BK=16, 256 threads, 8x8 per thread, FFMA2 inner product.
// Requires M%128==0, N%128==0, K%16==0 (holds for all uses here).
__global__ void __launch_bounds__(256) gemm_bias(const float* __restrict__ A,
                                                 const float* __restrict__ Bm,
                                                 const float* __restrict__ bias,
                                                 float* __restrict__ C,
                                                 int M, int N, int K) {
    __shared__ float As[16][128];
    __shared__ float Bs[16][128];
    const int tid = threadIdx.x;
    const int bm = blockIdx.y * 128, bn = blockIdx.x * 128;
    const int tx = tid & 15, ty = tid >> 4;

    unsigned long long acc[8][4];
#pragma unroll
    for (int i = 0; i < 8; i++)
#pragma unroll
        for (int j = 0; j < 4; j++) acc[i][j] = 0ull;

    const int ar = tid >> 2, akq = tid & 3;   // A-load role
    const int br = tid >> 5, bc = tid & 31;   // B-load role

    for (int k0 = 0; k0 < K; k0 += 16) {
#pragma unroll
        for (int i = 0; i < 2; i++) {
            int r = ar + i * 64;
            float4 v = *(const float4*)&A[(size_t)(bm + r) * K + k0 + akq * 4];
            As[akq * 4 + 0][r] = v.x; As[akq * 4 + 1][r] = v.y;
            As[akq * 4 + 2][r] = v.z; As[akq * 4 + 3][r] = v.w;
        }
#pragma unroll
        for (int i = 0; i < 2; i++) {
            int rr = br + i * 8;
            *(float4*)&Bs[rr][bc * 4] =
                *(const float4*)&Bm[(size_t)(k0 + rr) * N + bn + bc * 4];
        }
        __syncthreads();
#pragma unroll
        for (int kk = 0; kk < 16; kk++) {
            float4 a0 = *(const float4*)&As[kk][ty * 8];
            float4 a1 = *(const float4*)&As[kk][ty * 8 + 4];
            ulonglong2 b0 = *(const ulonglong2*)&Bs[kk][tx * 8];
            ulonglong2 b1 = *(const ulonglong2*)&Bs[kk][tx * 8 + 4];
            float aa[8] = {a0.x, a0.y, a0.z, a0.w, a1.x, a1.y, a1.z, a1.w};
#pragma unroll
            for (int i = 0; i < 8; i++) {
                unsigned long long ap = pk2(aa[i], aa[i]);
                fma2(acc[i][0], ap, b0.x);
                fma2(acc[i][1], ap, b0.y);
                fma2(acc[i][2], ap, b1.x);
                fma2(acc[i][3], ap, b1.y);
            }
        }
        __syncthreads();
    }

    float4 bsa = *(const float4*)&bias[bn + tx * 8];
    float4 bsb = *(const float4*)&bias[bn + tx * 8 + 4];
#pragma unroll
    for (int i = 0; i < 8; i++) {
        float2 p0 = up2(acc[i][0]), p1 = up2(acc[i][1]);
        float2 p2 = up2(acc[i][2]), p3 = up2(acc[i][3]);
        float4 o0 = make_float4(p0.x + bsa.x, p0.y + bsa.y, p1.x + bsa.z, p1.y + bsa.w);
        float4 o1 = make_float4(p2.x + bsb.x, p2.y + bsb.y, p3.x + bsb.z, p3.y + bsb.w);
        size_t m = (size_t)(bm + ty * 8 + i);
        *(float4*)&C[m * N + bn + tx * 8]     = o0;
        *(float4*)&C[m * N + bn + tx * 8 + 4] = o1;
    }
}

// ---------------- persistent LSTM scan ----------------
// grid = 128 CTAs (one wave, all resident), 128 threads.
// CTA `cta` owns hidden cols [4*cta, 4*cta+4). Thread (rp, q): rows {rp, rp+32}, hidden col q.
// Per step: stage h (transposed global -> smem, straight copy), GEMM over K=512 with
// U slice resident in smem, CTA-local elementwise LSTM update (c in registers),
// write h_new (transposed) + hidden_seq, one software grid barrier.
__global__ void __launch_bounds__(NTHR_SCAN, 1)
lstm_scan(const float* __restrict__ U, float* __restrict__ dout) {
    extern __shared__ float smem[];
    float* U_s = smem;                 // [512][16] : 16 = hcl*4 + gate
    float* h_s = smem + 512 * 16;      // [512][64] : h transposed, conflict-free
    float* xb  = h_s + 512 * 64;       // [64][17]  : xp exchange (pitch 17 = conflict-free)

    const int tid = threadIdx.x;
    const int q  = tid >> 5;           // 0..3 : warp id = hidden-col-local (and gate role in loads)
    const int rp = tid & 31;
    const int cta = blockIdx.x;
    const int hc = cta * 4 + q;        // this thread's hidden column

    // Load U slice once: U_s[k][hcl*4+g] = U[k][g*512 + cta*4 + hcl]
    for (int idx = tid; idx < 512 * 16; idx += NTHR_SCAN) {
        int k = idx >> 4, c = idx & 15;
        int hcl = c >> 2, g = c & 3;
        U_s[idx] = U[(size_t)k * G4 + g * H_ + cta * 4 + hcl];
    }

    float c0 = 0.0f, c1 = 0.0f;
    const ulonglong2* Up2 = ((const ulonglong2*)U_s) + q;   // Up2[k*4] -> 16B = 4 gate weights

    const size_t OUT_ELEMS = (size_t)B_ * T_ * O_;

    for (int s = 0; s < T_; s++) {
        // ---- stage h (L2 -> smem, bypass L1: other SMs wrote it) ----
        {
            const float4* hsrc = (const float4*)g_hbuf[s & 1];
            float4* hdst = (float4*)h_s;
            for (int i = tid; i < (H_ * B_ / 4); i += NTHR_SCAN)
                hdst[i] = __ldcg(&hsrc[i]);
        }
        // ---- xp loads: thread (rp,q) fetches float4 of 4 hidden cols for gate q, rows rp & rp+32 ----
        {
            size_t cb = (size_t)q * H_ + cta * 4;
            float4 x0 = __ldcg((const float4*)&g_xp[(size_t)(rp * T_ + s) * G4 + cb]);
            float4 x1 = __ldcg((const float4*)&g_xp[(size_t)((rp + 32) * T_ + s) * G4 + cb]);
            float* p0 = &xb[rp * 17 + q * 4];
            p0[0] = x0.x; p0[1] = x0.y; p0[2] = x0.z; p0[3] = x0.w;
            float* p1 = &xb[(rp + 32) * 17 + q * 4];
            p1[0] = x1.x; p1[1] = x1.y; p1[2] = x1.z; p1[3] = x1.w;
        }
        __syncthreads();   // h_s, xb (and first-iter U_s) ready

        // ---- init accumulators from xp (gate order: i,f,g,o) ----
        unsigned long long a0_if = pk2(xb[rp * 17 + 0 + q], xb[rp * 17 + 4 + q]);
        unsigned long long a0_go = pk2(xb[rp * 17 + 8 + q], xb[rp * 17 + 12 + q]);
        unsigned long long a1_if = pk2(xb[(rp + 32) * 17 + 0 + q], xb[(rp + 32) * 17 + 4 + q]);
        unsigned long long a1_go = pk2(xb[(rp + 32) * 17 + 8 + q], xb[(rp + 32) * 17 + 12 + q]);

        // ---- K=512 dot products (FFMA2) ----
#pragma unroll 8
        for (int k = 0; k < H_; k++) {
            float h0 = h_s[k * 64 + rp];
            float h1 = h_s[k * 64 + rp + 32];
            ulonglong2 uu = Up2[(size_t)k * 4];
            unsigned long long hp0 = pk2(h0, h0);
            unsigned long long hp1 = pk2(h1, h1);
            fma2(a0_if, hp0, uu.x);
            fma2(a0_go, hp0, uu.y);
            fma2(a1_if, hp1, uu.x);
            fma2(a1_go, hp1, uu.y);
        }

        // ---- elementwise LSTM cell (c lives in registers) ----
        float2 g0if = up2(a0_if), g0go = up2(a0_go);
        float2 g1if = up2(a1_if), g1go = up2(a1_go);

        float i0 = sigmoidf_(g0if.x), f0 = sigmoidf_(g0if.y);
        float gg0 = tanhf(g0go.x),    o0 = sigmoidf_(g0go.y);
        c0 = f0 * c0 + i0 * gg0;
        float h0n = o0 * tanhf(c0);

        float i1 = sigmoidf_(g1if.x), f1 = sigmoidf_(g1if.y);
        float gg1 = tanhf(g1go.x),    o1 = sigmoidf_(g1go.y);
        c1 = f1 * c1 + i1 * gg1;
        float h1n = o1 * tanhf(c1);

        // ---- write h_new (transposed buffer, coalesced) + hidden_seq ----
        float* hb = g_hbuf[(s + 1) & 1];
        hb[hc * 64 + rp]      = h0n;
        hb[hc * 64 + rp + 32] = h1n;
        g_hseq[(size_t)(rp * T_ + s) * H_ + hc]        = h0n;
        g_hseq[(size_t)((rp + 32) * T_ + s) * H_ + hc] = h1n;

        if (s == T_ - 1) {
            dout[OUT_ELEMS + (size_t)rp * H_ + hc]                      = h0n;
            dout[OUT_ELEMS + (size_t)(rp + 32) * H_ + hc]               = h1n;
            dout[OUT_ELEMS + (size_t)B_ * H_ + (size_t)rp * H_ + hc]        = c0;
            dout[OUT_ELEMS + (size_t)B_ * H_ + (size_t)(rp + 32) * H_ + hc] = c1;
        }

        // ---- grid barrier (all 128 CTAs resident: safe) ----
        __threadfence();
        __syncthreads();
        if (tid == 0) {
            atomicAdd(&g_bar, 1u);
            unsigned target = (unsigned)NCTA_SCAN * (unsigned)(s + 1);
            while (*(volatile unsigned*)&g_bar < target) { }
            __threadfence();
        }
        __syncthreads();
    }
}

// ---------------- launch ----------------
extern "C" void kernel_launch(void* const* d_in, const int* in_sizes, int n_in,
                              void* d_out, int out_size) {
    const float* x    = (const float*)d_in[0];
    const float* W    = (const float*)d_in[1];
    const float* U    = (const float*)d_in[2];
    const float* bias = (const float*)d_in[3];
    const float* Wl   = (const float*)d_in[4];
    const float* bl   = (const float*)d_in[5];
    float* out = (float*)d_out;

    void* xp_ptr = nullptr;
    void* hs_ptr = nullptr;
    cudaGetSymbolAddress(&xp_ptr, g_xp);
    cudaGetSymbolAddress(&hs_ptr, g_hseq);

    const int SCAN_SMEM = (512 * 16 + 512 * 64 + 64 * 17) * (int)sizeof(float);  // 168192 B
    cudaFuncSetAttribute(lstm_scan, cudaFuncAttributeMaxDynamicSharedMemorySize, SCAN_SMEM);

    // 1) reset h0 / barrier
    init_kernel<<<256, 256>>>();
    // 2) x_proj = x @ W + bias   : [32768,256]@[256,2048]
    gemm_bias<<<dim3(G4 / 128, (B_ * T_) / 128), 256>>>(x, W, bias, (float*)xp_ptr,
                                                        B_ * T_, G4, I_);
    // 3) recurrent scan (persistent, 512 steps)
    lstm_scan<<<NCTA_SCAN, NTHR_SCAN, SCAN_SMEM>>>(U, out);
    // 4) out = hidden_seq @ Wl + bl : [32768,512]@[512,256]
    gemm_bias<<<dim3(O_ / 128, (B_ * T_) / 128), 256>>>((const float*)hs_ptr, Wl, bl, out,
                                                        B_ * T_, O_, H_);
}

// round 2
// speedup vs baseline: 1.1000x; 1.1000x over previous
#include <cuda_runtime.h>
#include <cstdint>
#include <cstddef>

#define B_  64
#define T_  512
#define I_  256
#define H_  512
#define G4  2048   // 4*H
#define O_  256

#define NCTA_SCAN 128
#define NTHR_SCAN 512

// ---------------- static scratch (allocation-free per rules) ----------------
__device__ float g_xp[(size_t)B_ * T_ * G4];     // x@W + bias, [B*T, 4H]
__device__ float g_hseq[(size_t)B_ * T_ * H_];   // hidden_seq [B*T, H]
__device__ float g_hbuf[2][H_ * B_];             // h double buffer, TRANSPOSED [k][b]
__device__ unsigned g_bar;

// ---------------- packed fp32x2 helpers (sm_103a FFMA2) ----------------
__device__ __forceinline__ unsigned long long pk2(float x, float y) {
    unsigned long long r;
    asm("mov.b64 %0, {%1,%2};" : "=l"(r) : "f"(x), "f"(y));
    return r;
}
__device__ __forceinline__ void fma2(unsigned long long& d, unsigned long long a, unsigned long long b) {
    asm("fma.rn.f32x2 %0, %1, %2, %0;" : "+l"(d) : "l"(a), "l"(b));
}
__device__ __forceinline__ float2 up2(unsigned long long v) {
    float lo, hi;
    asm("mov.b64 {%0,%1}, %2;" : "=f"(lo), "=f"(hi) : "l"(v));
    return make_float2(lo, hi);
}

__device__ __forceinline__ float sigmoidf_(float x) { return 1.0f / (1.0f + expf(-x)); }

// ---------------- init: zero h0 + barrier counter (every launch) ----------------
__global__ void init_kernel() {
    int i = blockIdx.x * blockDim.x + threadIdx.x;
    if (i < 2 * H_ * B_) ((float*)g_hbuf)[i] = 0.0f;
    if (i == 0) g_bar = 0u;
}

// ---------------- generic fp32 GEMM + bias: C[M,N] = A[M,K]@B[K,N] + bias ----------------
__global__ void __launch_bounds__(256) gemm_bias(const float* __restrict__ A,
                                                 const float* __restrict__ Bm,
                                                 const float* __restrict__ bias,
                                                 float* __restrict__ C,
                                                 int M, int N, int K) {
    __shared__ float As[16][128];
    __shared__ float Bs[16][128];
    const int tid = threadIdx.x;
    const int bm = blockIdx.y * 128, bn = blockIdx.x * 128;
    const int tx = tid & 15, ty = tid >> 4;

    unsigned long long acc[8][4];
#pragma unroll
    for (int i = 0; i < 8; i++)
#pragma unroll
        for (int j = 0; j < 4; j++) acc[i][j] = 0ull;

    const int ar = tid >> 2, akq = tid & 3;
    const int br = tid >> 5, bc = tid & 31;

    for (int k0 = 0; k0 < K; k0 += 16) {
#pragma unroll
        for (int i = 0; i < 2; i++) {
            int r = ar + i * 64;
            float4 v = *(const float4*)&A[(size_t)(bm + r) * K + k0 + akq * 4];
            As[akq * 4 + 0][r] = v.x; As[akq * 4 + 1][r] = v.y;
            As[akq * 4 + 2][r] = v.z; As[akq * 4 + 3][r] = v.w;
        }
#pragma unroll
        for (int i = 0; i < 2; i++) {
            int rr = br + i * 8;
            *(float4*)&Bs[rr][bc * 4] =
                *(const float4*)&Bm[(size_t)(k0 + rr) * N + bn + bc * 4];
        }
        __syncthreads();
#pragma unroll
        for (int kk = 0; kk < 16; kk++) {
            float4 a0 = *(const float4*)&As[kk][ty * 8];
            float4 a1 = *(const float4*)&As[kk][ty * 8 + 4];
            ulonglong2 b0 = *(const ulonglong2*)&Bs[kk][tx * 8];
            ulonglong2 b1 = *(const ulonglong2*)&Bs[kk][tx * 8 + 4];
            float aa[8] = {a0.x, a0.y, a0.z, a0.w, a1.x, a1.y, a1.z, a1.w};
#pragma unroll
            for (int i = 0; i < 8; i++) {
                unsigned long long ap = pk2(aa[i], aa[i]);
                fma2(acc[i][0], ap, b0.x);
                fma2(acc[i][1], ap, b0.y);
                fma2(acc[i][2], ap, b1.x);
                fma2(acc[i][3], ap, b1.y);
            }
        }
        __syncthreads();
    }

    float4 bsa = *(const float4*)&bias[bn + tx * 8];
    float4 bsb = *(const float4*)&bias[bn + tx * 8 + 4];
#pragma unroll
    for (int i = 0; i < 8; i++) {
        float2 p0 = up2(acc[i][0]), p1 = up2(acc[i][1]);
        float2 p2 = up2(acc[i][2]), p3 = up2(acc[i][3]);
        float4 o0 = make_float4(p0.x + bsa.x, p0.y + bsa.y, p1.x + bsa.z, p1.y + bsa.w);
        float4 o1 = make_float4(p2.x + bsb.x, p2.y + bsb.y, p3.x + bsb.z, p3.y + bsb.w);
        size_t m = (size_t)(bm + ty * 8 + i);
        *(float4*)&C[m * N + bn + tx * 8]     = o0;
        *(float4*)&C[m * N + bn + tx * 8 + 4] = o1;
    }
}

// ---------------- persistent LSTM scan (512 threads, K-split 4) ----------------
// grid = 128 CTAs (one wave), 512 threads = 16 warps.
// tid -> rp = tid&31 (lane), q = (tid>>5)&3 (hidden col local), kh = tid>>7 (K quarter).
// CTA owns hidden cols [4*cta, 4*cta+4). Thread computes col q, batch rows {2rp, 2rp+1},
// over K slice [kh*128, kh*128+128). Partials reduced via smem; kh==0 does the cell.
// U stored in smem DUPLICATED as (u,u) pairs -> FFMA2 operands load directly, no movs.
// h staged transposed [k][b] so (h_b0,h_b1) for adjacent rows is one LDS.64.
__global__ void __launch_bounds__(NTHR_SCAN, 1)
lstm_scan(const float* __restrict__ U, float* __restrict__ dout) {
    extern __shared__ float smem[];
    float* U_s  = smem;                     // [512][4 q][4 g][2 dup] = 16384 floats (64 KB)
    float* h_s  = U_s + 512 * 32;           // [512][64] transposed h (128 KB)
    float* xb   = h_s + 512 * 64;           // [64][17] xp exchange
    float* part = xb + 64 * 17;             // [3][128][4] float2 partials (12 KB)

    const int tid = threadIdx.x;
    const int rp  = tid & 31;
    const int q   = (tid >> 5) & 3;
    const int kh  = tid >> 7;
    const int cta = blockIdx.x;
    const int hc  = cta * 4 + q;

    // Load U duplicated: U_s[((k*4+q)*4+g)*2 + d] = U[k][g*512 + cta*4 + q]
    for (int idx = tid; idx < 512 * 32; idx += NTHR_SCAN) {
        int k = idx >> 5, r = idx & 31;
        int qq = r >> 3, g = (r >> 1) & 3;
        U_s[idx] = U[(size_t)k * G4 + g * H_ + cta * 4 + qq];
    }

    float c0 = 0.0f, c1 = 0.0f;
    const ulonglong2* Uq = ((const ulonglong2*)U_s) + q * 2;   // Uq[k*8], Uq[k*8+1]
    const size_t OUT_ELEMS = (size_t)B_ * T_ * O_;
    const int b0 = 2 * rp, b1 = 2 * rp + 1;

    for (int s = 0; s < T_; s++) {
        // ---- stage h (L2 -> smem; .cg required: buffer alternates, avoid stale L1) ----
        {
            const float4* hsrc = (const float4*)g_hbuf[s & 1];
            float4* hdst = (float4*)h_s;
#pragma unroll
            for (int i = 0; i < (H_ * B_ / 4) / NTHR_SCAN; i++)
                hdst[tid + i * NTHR_SCAN] = __ldcg(&hsrc[tid + i * NTHR_SCAN]);
        }
        // ---- xp staging (kh==0 threads): gate-q block of 4 cols, rows rp & rp+32 ----
        if (kh == 0) {
            size_t cb = (size_t)q * H_ + cta * 4;
            float4 x0 = __ldcg((const float4*)&g_xp[(size_t)(rp * T_ + s) * G4 + cb]);
            float4 x1 = __ldcg((const float4*)&g_xp[(size_t)((rp + 32) * T_ + s) * G4 + cb]);
            float* p0 = &xb[rp * 17 + q * 4];
            p0[0] = x0.x; p0[1] = x0.y; p0[2] = x0.z; p0[3] = x0.w;
            float* p1 = &xb[(rp + 32) * 17 + q * 4];
            p1[0] = x1.x; p1[1] = x1.y; p1[2] = x1.z; p1[3] = x1.w;
        }
        __syncthreads();

        // ---- accumulators: packed (row b0, row b1) per gate; kh==0 seeds from xp ----
        unsigned long long a0, a1, a2, a3;
        if (kh == 0) {
            a0 = pk2(xb[b0 * 17 + 0 + q],  xb[b1 * 17 + 0 + q]);
            a1 = pk2(xb[b0 * 17 + 4 + q],  xb[b1 * 17 + 4 + q]);
            a2 = pk2(xb[b0 * 17 + 8 + q],  xb[b1 * 17 + 8 + q]);
            a3 = pk2(xb[b0 * 17 + 12 + q], xb[b1 * 17 + 12 + q]);
        } else {
            a0 = a1 = a2 = a3 = 0ull;
        }

        // ---- K/4 dot products: 1 LDS.64 + 2 LDS.128 + 4 FFMA2 per k ----
        const unsigned long long* hp2 = (const unsigned long long*)h_s + rp; // + k*32
        const int k0 = kh * 128;
#pragma unroll 8
        for (int k = k0; k < k0 + 128; k++) {
            unsigned long long hp = hp2[(size_t)k * 32];
            ulonglong2 uif = Uq[(size_t)k * 8];
            ulonglong2 ugo = Uq[(size_t)k * 8 + 1];
            fma2(a0, hp, uif.x);
            fma2(a1, hp, uif.y);
            fma2(a2, hp, ugo.x);
            fma2(a3, hp, ugo.y);
        }

        // ---- K-split reduction ----
        if (kh > 0) {
            float2* pp = (float2*)part + ((size_t)(kh - 1) * 128 + q * 32 + rp) * 4;
            pp[0] = up2(a0); pp[1] = up2(a1); pp[2] = up2(a2); pp[3] = up2(a3);
        }
        __syncthreads();

        if (kh == 0) {
            float2 A0 = up2(a0), A1 = up2(a1), A2 = up2(a2), A3 = up2(a3);
#pragma unroll
            for (int kk = 0; kk < 3; kk++) {
                const float2* pp = (const float2*)part + ((size_t)kk * 128 + q * 32 + rp) * 4;
                float2 p0 = pp[0], p1 = pp[1], p2 = pp[2], p3 = pp[3];
                A0.x += p0.x; A0.y += p0.y;
                A1.x += p1.x; A1.y += p1.y;
                A2.x += p2.x; A2.y += p2.y;
                A3.x += p3.x; A3.y += p3.y;
            }
            // ---- LSTM cell (gate order i,f,g,o) ----
            float i0 = sigmoidf_(A0.x), i1 = sigmoidf_(A0.y);
            float f0 = sigmoidf_(A1.x), f1 = sigmoidf_(A1.y);
            float g0 = tanhf(A2.x),     g1 = tanhf(A2.y);
            float o0 = sigmoidf_(A3.x), o1 = sigmoidf_(A3.y);
            c0 = f0 * c0 + i0 * g0;
            c1 = f1 * c1 + i1 * g1;
            float h0n = o0 * tanhf(c0);
            float h1n = o1 * tanhf(c1);

            // h_new transposed (coalesced float2) + hidden_seq
            float2* hb2 = (float2*)g_hbuf[(s + 1) & 1];
            hb2[hc * 32 + rp] = make_float2(h0n, h1n);
            g_hseq[(size_t)(b0 * T_ + s) * H_ + hc] = h0n;
            g_hseq[(size_t)(b1 * T_ + s) * H_ + hc] = h1n;

            if (s == T_ - 1) {
                dout[OUT_ELEMS + (size_t)b0 * H_ + hc] = h0n;
                dout[OUT_ELEMS + (size_t)b1 * H_ + hc] = h1n;
                dout[OUT_ELEMS + (size_t)B_ * H_ + (size_t)b0 * H_ + hc] = c0;
                dout[OUT_ELEMS + (size_t)B_ * H_ + (size_t)b1 * H_ + hc] = c1;
            }
        }

        // ---- grid barrier (all 128 CTAs resident: safe) ----
        __threadfence();
        __syncthreads();
        if (tid == 0) {
            atomicAdd(&g_bar, 1u);
            unsigned target = (unsigned)NCTA_SCAN * (unsigned)(s + 1);
            while (*(volatile unsigned*)&g_bar < target) { }
            __threadfence();
        }
        __syncthreads();
    }
}

// ---------------- launch ----------------
extern "C" void kernel_launch(void* const* d_in, const int* in_sizes, int n_in,
                              void* d_out, int out_size) {
    const float* x    = (const float*)d_in[0];
    const float* W    = (const float*)d_in[1];
    const float* U    = (const float*)d_in[2];
    const float* bias = (const float*)d_in[3];
    const float* Wl   = (const float*)d_in[4];
    const float* bl   = (const float*)d_in[5];
    float* out = (float*)d_out;

    void* xp_ptr = nullptr;
    void* hs_ptr = nullptr;
    cudaGetSymbolAddress(&xp_ptr, g_xp);
    cudaGetSymbolAddress(&hs_ptr, g_hseq);

    const int SCAN_SMEM = (512 * 32 + 512 * 64 + 64 * 17 + 3 * 128 * 8) * (int)sizeof(float); // 213248 B
    cudaFuncSetAttribute(lstm_scan, cudaFuncAttributeMaxDynamicSharedMemorySize, SCAN_SMEM);

    // 1) reset h0 / barrier
    init_kernel<<<256, 256>>>();
    // 2) x_proj = x @ W + bias : [32768,256]@[256,2048]
    gemm_bias<<<dim3(G4 / 128, (B_ * T_) / 128), 256>>>(x, W, bias, (float*)xp_ptr,
                                                        B_ * T_, G4, I_);
    // 3) recurrent scan (persistent, 512 steps)
    lstm_scan<<<NCTA_SCAN, NTHR_SCAN, SCAN_SMEM>>>(U, out);
    // 4) out = hidden_seq @ Wl + bl : [32768,512]@[512,256]
    gemm_bias<<<dim3(O_ / 128, (B_ * T_) / 128), 256>>>((const float*)hs_ptr, Wl, bl, out,
                                                        B_ * T_, O_, H_);
}